// round 3
// baseline (speedup 1.0000x reference)
#include <cuda_runtime.h>
#include <cuda_bf16.h>

// Channels-last scratch: per level [B][H*W][256]. Bases in floats.
#define FB0 0
#define FB1 16777216            // + 4*128*128*256
#define FB2 20971520            // + 4*64*64*256
#define FB3 22020096            // + 4*32*32*256
#define FB4 22282240            // + 4*16*16*256
#define FT_TOTAL 22347776       // + 4*8*8*256

__device__ float g_ft[FT_TOTAL];

// ---------------- merged transpose: all 5 levels, [b][c][s] -> [b][s][c] ----------------
// Tile = 32 channels x 32 flat-spatial, 256 threads. Blocks per level = H*W.
__global__ __launch_bounds__(256) void transpose_all(
    const float* __restrict__ f0, const float* __restrict__ f1,
    const float* __restrict__ f2, const float* __restrict__ f3,
    const float* __restrict__ f4)
{
    __shared__ float tile[32][33];
    int bid = blockIdx.x;
    const float* in; int HH, base, lsh;
    if (bid < 16384)      { in = f0; HH = 16384; base = FB0; lsh = 9; }
    else if (bid < 20480) { in = f1; HH = 4096;  base = FB1; lsh = 7; bid -= 16384; }
    else if (bid < 21504) { in = f2; HH = 1024;  base = FB2; lsh = 5; bid -= 20480; }
    else if (bid < 21760) { in = f3; HH = 256;   base = FB3; lsh = 3; bid -= 21504; }
    else                  { in = f4; HH = 64;    base = FB4; lsh = 1; bid -= 21760; }

    const int st = bid & ((1 << lsh) - 1);     // spatial tile (HH/32 tiles)
    const int r  = bid >> lsh;
    const int ct = r & 7;                      // channel tile (8)
    const int b  = r >> 3;                     // batch (4)
    const int tx = threadIdx.x & 31, ty = threadIdx.x >> 5;

    const float* ip = in + (long)(b * 256 + ct * 32) * HH + st * 32;
    #pragma unroll
    for (int j = 0; j < 4; j++)
        tile[ty + 8*j][tx] = ip[(long)(ty + 8*j) * HH + tx];
    __syncthreads();

    float* op = g_ft + base + ((long)b * HH + st * 32) * 256 + ct * 32;
    #pragma unroll
    for (int j = 0; j < 4; j++)
        op[(long)(ty + 8*j) * 256 + tx] = tile[tx][ty + 8*j];
}

// ---------------- main kernel: block = ROI, warp = (ox, ch-half) ----------------
#define SB_PITCH 260
#define SB_FLOATS (49 * SB_PITCH)

__global__ __launch_bounds__(448, 4) void msroi3(
    const float* __restrict__ rois, float* __restrict__ out)
{
    extern __shared__ float sbuf[];                 // [49][SB_PITCH]
    __shared__ int   sxo0[14], sxo1[14], syo0[14], syo1[14];
    __shared__ float swx0[14], swx1[14], swy0[14], swy1[14];

    const int roi = blockIdx.x;                     // b*256 + n
    const int b   = roi >> 8;
    const int tid = threadIdx.x;

    if (tid < 28) {
        const float rx1 = rois[roi*4+0], ry1 = rois[roi*4+1];
        const float rx2 = rois[roi*4+2], ry2 = rois[roi*4+3];
        const float area = (rx2 - rx1) * (ry2 - ry1);
        float lv = floorf(4.0f + log2f(sqrtf(area) / 224.0f + 1e-6f));
        lv = fminf(fmaxf(lv, 2.0f), 6.0f);
        const int lvl = (int)lv - 2;

        int H, base; float scale;
        switch (lvl) {
            case 0:  H = 128; base = FB0; scale = 0.25f;     break;
            case 1:  H = 64;  base = FB1; scale = 0.125f;    break;
            case 2:  H = 32;  base = FB2; scale = 0.0625f;   break;
            case 3:  H = 16;  base = FB3; scale = 0.03125f;  break;
            default: H = 8;   base = FB4; scale = 0.015625f; break;
        }
        const float x1 = rx1 * scale, y1 = ry1 * scale;
        const float bw = fmaxf(rx2 * scale - x1, 1.0f) / 7.0f;
        const float bh = fmaxf(ry2 * scale - y1, 1.0f) / 7.0f;

        const bool isY = tid >= 14;
        const int  i   = isY ? tid - 14 : tid;
        const float g = 0.25f + 0.5f * (float)i;              // == k + (sr+0.5)/2
        const float p = isY ? (y1 + g * bh) : (x1 + g * bw);
        const float v = (p >= -1.0f && p <= (float)H) ? 0.5f : 0.0f;  // validity * sqrt(2x2 mean)
        const float pc = fminf(fmaxf(p, 0.0f), (float)(H - 1));
        const float pf = floorf(pc);
        const float l  = pc - pf;
        const int p0 = (int)pf;
        const int p1 = min(p0 + 1, H - 1);
        if (isY) {
            syo0[i] = base + ((b * H + p0) * H) * 256;
            syo1[i] = base + ((b * H + p1) * H) * 256;
            swy0[i] = (1.0f - l) * v;  swy1[i] = l * v;
        } else {
            sxo0[i] = p0 * 256;  sxo1[i] = p1 * 256;
            swx0[i] = (1.0f - l) * v;  swx1[i] = l * v;
        }
    }
    __syncthreads();

    const int warp = tid >> 5, lane = tid & 31;
    const int ox   = warp % 7;                      // 0..6
    const int ch   = (warp / 7) * 128 + lane * 4;   // warp covers 128 contiguous ch

    #pragma unroll 1
    for (int oy = 0; oy < 7; oy++) {
        float ax = 0.f, ay = 0.f, az = 0.f, aw = 0.f;
        #pragma unroll
        for (int sy = 0; sy < 2; sy++) {
            const int gy = 2 * oy + sy;
            const float* __restrict__ r0 = g_ft + syo0[gy] + ch;
            const float* __restrict__ r1 = g_ft + syo1[gy] + ch;
            const float wy0 = swy0[gy], wy1 = swy1[gy];
            #pragma unroll
            for (int sx = 0; sx < 2; sx++) {
                const int gx  = 2 * ox + sx;
                const int xo0 = sxo0[gx], xo1 = sxo1[gx];
                const float w00 = wy0 * swx0[gx];
                const float w01 = wy0 * swx1[gx];
                const float w10 = wy1 * swx0[gx];
                const float w11 = wy1 * swx1[gx];
                const float4 t00 = *(const float4*)(r0 + xo0);
                const float4 t01 = *(const float4*)(r0 + xo1);
                const float4 t10 = *(const float4*)(r1 + xo0);
                const float4 t11 = *(const float4*)(r1 + xo1);
                ax += w00*t00.x + w01*t01.x + w10*t10.x + w11*t11.x;
                ay += w00*t00.y + w01*t01.y + w10*t10.y + w11*t11.y;
                az += w00*t00.z + w01*t01.z + w10*t10.z + w11*t11.z;
                aw += w00*t00.w + w01*t01.w + w10*t10.w + w11*t11.w;
            }
        }
        *(float4*)(sbuf + (oy * 7 + ox) * SB_PITCH + ch) = make_float4(ax, ay, az, aw);
    }
    __syncthreads();

    // Coalesced flush: runs of 49 consecutive floats per channel.
    float* __restrict__ op = out + (long)roi * 12544;
    #pragma unroll
    for (int it = 0; it < 28; it++) {
        const int f  = tid + it * 448;              // 12544 = 448*28
        const int c2 = f / 49;
        const int b2 = f - c2 * 49;
        op[f] = sbuf[b2 * SB_PITCH + c2];
    }
}

extern "C" void kernel_launch(void* const* d_in, const int* in_sizes, int n_in,
                              void* d_out, int out_size) {
    const float* f0   = (const float*)d_in[0];
    const float* f1   = (const float*)d_in[1];
    const float* f2   = (const float*)d_in[2];
    const float* f3   = (const float*)d_in[3];
    const float* f4   = (const float*)d_in[4];
    const float* rois = (const float*)d_in[5];
    float* out        = (float*)d_out;

    static bool attr_done = false;
    if (!attr_done) {
        cudaFuncSetAttribute(msroi3, cudaFuncAttributeMaxDynamicSharedMemorySize,
                             SB_FLOATS * (int)sizeof(float));
        attr_done = true;
    }

    transpose_all<<<21824, 256>>>(f0, f1, f2, f3, f4);
    msroi3<<<1024, 448, SB_FLOATS * sizeof(float)>>>(rois, out);
}

// round 6
// speedup vs baseline: 2.1216x; 2.1216x over previous
#include <cuda_runtime.h>
#include <cuda_fp16.h>
#include <cuda_bf16.h>

// Channels-last fp16 scratch: per level [B][H*W][256]. Bases in elements.
#define FB0 0
#define FB1 16777216            // + 4*128*128*256
#define FB2 20971520            // + 4*64*64*256
#define FB3 22020096            // + 4*32*32*256
#define FB4 22282240            // + 4*16*16*256
#define FT_TOTAL 22347776       // + 4*8*8*256

__device__ __half g_fth[FT_TOTAL];   // ~44.7 MB — fits L2 with room to spare

// ---------------- merged transpose: all 5 levels, [b][c][s] -> [b][s][c] fp16 ----------------
__global__ __launch_bounds__(256) void transpose_all(
    const float* __restrict__ f0, const float* __restrict__ f1,
    const float* __restrict__ f2, const float* __restrict__ f3,
    const float* __restrict__ f4)
{
    __shared__ float tile[32][33];
    int bid = blockIdx.x;
    const float* in; int HH, base, lsh;
    if (bid < 16384)      { in = f0; HH = 16384; base = FB0; lsh = 9; }
    else if (bid < 20480) { in = f1; HH = 4096;  base = FB1; lsh = 7; bid -= 16384; }
    else if (bid < 21504) { in = f2; HH = 1024;  base = FB2; lsh = 5; bid -= 20480; }
    else if (bid < 21760) { in = f3; HH = 256;   base = FB3; lsh = 3; bid -= 21504; }
    else                  { in = f4; HH = 64;    base = FB4; lsh = 1; bid -= 21760; }

    const int st = bid & ((1 << lsh) - 1);     // spatial tile
    const int r  = bid >> lsh;
    const int ct = r & 7;                      // channel tile (8)
    const int b  = r >> 3;                     // batch (4)
    const int tx = threadIdx.x & 31, ty = threadIdx.x >> 5;

    const float* ip = in + (long)(b * 256 + ct * 32) * HH + st * 32;
    #pragma unroll
    for (int j = 0; j < 4; j++)
        tile[ty + 8*j][tx] = ip[(long)(ty + 8*j) * HH + tx];
    __syncthreads();

    __half* op = g_fth + base + ((long)b * HH + st * 32) * 256 + ct * 32;
    #pragma unroll
    for (int j = 0; j < 4; j++)
        op[(long)(ty + 8*j) * 256 + tx] = __float2half_rn(tile[tx][ty + 8*j]);
}

// ---------------- main kernel: R2-proven mapping, fp16 taps ----------------
#define SB_PITCH 132
__global__ __launch_bounds__(256) void msroi4(
    const float* __restrict__ rois, float* __restrict__ out)
{
    __shared__ int   sxo0[14], sxo1[14], syo0[14], syo1[14];
    __shared__ float swx0[14], swx1[14], swy0[14], swy1[14];
    __shared__ float sbuf[49 * SB_PITCH];           // one 128-ch output tile

    const int roi = blockIdx.x;                     // b*256 + n
    const int b   = roi >> 8;
    const int tid = threadIdx.x;

    if (tid < 28) {
        const float rx1 = rois[roi*4+0], ry1 = rois[roi*4+1];
        const float rx2 = rois[roi*4+2], ry2 = rois[roi*4+3];
        const float area = (rx2 - rx1) * (ry2 - ry1);
        float lv = floorf(4.0f + log2f(sqrtf(area) / 224.0f + 1e-6f));
        lv = fminf(fmaxf(lv, 2.0f), 6.0f);
        const int lvl = (int)lv - 2;

        int H, base; float scale;
        switch (lvl) {
            case 0:  H = 128; base = FB0; scale = 0.25f;     break;
            case 1:  H = 64;  base = FB1; scale = 0.125f;    break;
            case 2:  H = 32;  base = FB2; scale = 0.0625f;   break;
            case 3:  H = 16;  base = FB3; scale = 0.03125f;  break;
            default: H = 8;   base = FB4; scale = 0.015625f; break;
        }
        const float x1 = rx1 * scale, y1 = ry1 * scale;
        const float bw = fmaxf(rx2 * scale - x1, 1.0f) / 7.0f;
        const float bh = fmaxf(ry2 * scale - y1, 1.0f) / 7.0f;

        const bool isY = tid >= 14;
        const int  i   = isY ? tid - 14 : tid;
        const float g = 0.25f + 0.5f * (float)i;              // == k + (sr+0.5)/2
        const float p = isY ? (y1 + g * bh) : (x1 + g * bw);
        const float v = (p >= -1.0f && p <= (float)H) ? 0.5f : 0.0f;  // validity * sqrt(2x2 mean)
        const float pc = fminf(fmaxf(p, 0.0f), (float)(H - 1));
        const float pf = floorf(pc);
        const float l  = pc - pf;
        const int p0 = (int)pf;
        const int p1 = min(p0 + 1, H - 1);
        if (isY) {
            syo0[i] = base + ((b * H + p0) * H) * 256;
            syo1[i] = base + ((b * H + p1) * H) * 256;
            swy0[i] = (1.0f - l) * v;  swy1[i] = l * v;
        } else {
            sxo0[i] = p0 * 256;  sxo1[i] = p1 * 256;
            swx0[i] = (1.0f - l) * v;  swx1[i] = l * v;
        }
    }
    __syncthreads();

    const int c8 = (tid & 15) * 8;   // 8-channel oct within a 128-ch tile
    const int bg = tid >> 4;         // 16 bin groups

    for (int ct = 0; ct < 2; ct++) {
        const int cofs = ct * 128 + c8;

        for (int bin = bg; bin < 49; bin += 16) {
            const int oy = bin / 7;
            const int ox = bin - oy * 7;
            float a0=0.f,a1=0.f,a2=0.f,a3=0.f,a4=0.f,a5=0.f,a6=0.f,a7=0.f;
            #pragma unroll
            for (int sy = 0; sy < 2; sy++) {
                const int gy = 2 * oy + sy;
                const __half* __restrict__ r0 = g_fth + syo0[gy] + cofs;
                const __half* __restrict__ r1 = g_fth + syo1[gy] + cofs;
                const float wy0 = swy0[gy], wy1 = swy1[gy];
                #pragma unroll
                for (int sx = 0; sx < 2; sx++) {
                    const int gx  = 2 * ox + sx;
                    const int xo0 = sxo0[gx], xo1 = sxo1[gx];
                    const float w00 = wy0 * swx0[gx];
                    const float w01 = wy0 * swx1[gx];
                    const float w10 = wy1 * swx0[gx];
                    const float w11 = wy1 * swx1[gx];
                    const uint4 q00 = *(const uint4*)(r0 + xo0);
                    const uint4 q01 = *(const uint4*)(r0 + xo1);
                    const uint4 q10 = *(const uint4*)(r1 + xo0);
                    const uint4 q11 = *(const uint4*)(r1 + xo1);
                    #pragma unroll
                    for (int k = 0; k < 4; k++) {
                        const float2 f00 = __half22float2(((const __half2*)&q00)[k]);
                        const float2 f01 = __half22float2(((const __half2*)&q01)[k]);
                        const float2 f10 = __half22float2(((const __half2*)&q10)[k]);
                        const float2 f11 = __half22float2(((const __half2*)&q11)[k]);
                        const float lo = w00*f00.x + w01*f01.x + w10*f10.x + w11*f11.x;
                        const float hi = w00*f00.y + w01*f01.y + w10*f10.y + w11*f11.y;
                        switch (k) {
                            case 0: a0 += lo; a1 += hi; break;
                            case 1: a2 += lo; a3 += hi; break;
                            case 2: a4 += lo; a5 += hi; break;
                            default: a6 += lo; a7 += hi; break;
                        }
                    }
                }
            }
            float* sp = sbuf + bin * SB_PITCH + c8;
            *(float4*)(sp    ) = make_float4(a0, a1, a2, a3);
            *(float4*)(sp + 4) = make_float4(a4, a5, a6, a7);
        }
        __syncthreads();

        // coalesced rewrite of this 128-channel tile into [c][bin] order
        float* __restrict__ op = out + (long)roi * 12544 + ct * 6272;
        for (int o = tid; o < 6272; o += 256) {
            const int c2 = o / 49;
            const int b2 = o - c2 * 49;
            op[o] = sbuf[b2 * SB_PITCH + c2];
        }
        __syncthreads();
    }
}

extern "C" void kernel_launch(void* const* d_in, const int* in_sizes, int n_in,
                              void* d_out, int out_size) {
    const float* f0   = (const float*)d_in[0];
    const float* f1   = (const float*)d_in[1];
    const float* f2   = (const float*)d_in[2];
    const float* f3   = (const float*)d_in[3];
    const float* f4   = (const float*)d_in[4];
    const float* rois = (const float*)d_in[5];
    float* out        = (float*)d_out;

    transpose_all<<<21824, 256>>>(f0, f1, f2, f3, f4);
    msroi4<<<1024, 256>>>(rois, out);
}

// round 7
// speedup vs baseline: 2.3001x; 1.0841x over previous
#include <cuda_runtime.h>
#include <cuda_fp16.h>
#include <cuda_bf16.h>

// Channels-last fp16 scratch: per level [B][H*W][256]. Bases in elements.
#define FB0 0
#define FB1 16777216            // + 4*128*128*256
#define FB2 20971520            // + 4*64*64*256
#define FB3 22020096            // + 4*32*32*256
#define FB4 22282240            // + 4*16*16*256
#define FT_TOTAL 22347776       // + 4*8*8*256

__device__ __half g_fth[FT_TOTAL];   // ~44.7 MB — resident in L2

// half2 -> packed f32x2 in one b64 (2 CVT, pack is free reg-pairing)
__device__ __forceinline__ unsigned long long h2f2(__half2 h) {
    unsigned long long r;
    unsigned int u = *(unsigned int*)&h;
    asm("{.reg .b16 a, b;\n\t"
        ".reg .f32 lo, hi;\n\t"
        "mov.b32 {a, b}, %1;\n\t"
        "cvt.f32.f16 lo, a;\n\t"
        "cvt.f32.f16 hi, b;\n\t"
        "mov.b64 %0, {lo, hi};}\n\t" : "=l"(r) : "r"(u));
    return r;
}
__device__ __forceinline__ void addf2(unsigned long long& acc, unsigned long long v) {
    asm("add.rn.f32x2 %0, %0, %1;" : "+l"(acc) : "l"(v));
}
__device__ __forceinline__ float2 unpackf2(unsigned long long v) {
    float2 f;
    asm("mov.b64 {%0, %1}, %2;" : "=f"(f.x), "=f"(f.y) : "l"(v));
    return f;
}

// ---------------- merged transpose: all 5 levels, [b][c][s] -> [b][s][c] fp16 ----------------
// Tile = 32 channels x 32 flat-spatial; float4 loads, half2 stores.
__global__ __launch_bounds__(256) void transpose_all(
    const float* __restrict__ f0, const float* __restrict__ f1,
    const float* __restrict__ f2, const float* __restrict__ f3,
    const float* __restrict__ f4)
{
    __shared__ float tile[32][33];      // [ch][spatial]
    int bid = blockIdx.x;
    const float* in; int HH, base, lsh;
    if (bid < 16384)      { in = f0; HH = 16384; base = FB0; lsh = 9; }
    else if (bid < 20480) { in = f1; HH = 4096;  base = FB1; lsh = 7; bid -= 16384; }
    else if (bid < 21504) { in = f2; HH = 1024;  base = FB2; lsh = 5; bid -= 20480; }
    else if (bid < 21760) { in = f3; HH = 256;   base = FB3; lsh = 3; bid -= 21504; }
    else                  { in = f4; HH = 64;    base = FB4; lsh = 1; bid -= 21760; }

    const int st = bid & ((1 << lsh) - 1);     // spatial tile
    const int r  = bid >> lsh;
    const int ct = r & 7;                      // channel tile (8)
    const int b  = r >> 3;                     // batch (4)
    const int tid = threadIdx.x;

    // Load: one float4 (4 spatial) per thread.
    const int lc = tid >> 3;                   // channel 0..31
    const int ls = (tid & 7) * 4;              // spatial 0..28
    const float4 v = *(const float4*)(in + (long)(b * 256 + ct * 32 + lc) * HH + st * 32 + ls);
    tile[lc][ls + 0] = v.x;
    tile[lc][ls + 1] = v.y;
    tile[lc][ls + 2] = v.z;
    tile[lc][ls + 3] = v.w;
    __syncthreads();

    // Store: half2 (2 channels) per thread, 2 spatial rows per thread.
    __half* op = g_fth + base + ((long)b * HH + st * 32) * 256 + ct * 32;
    const int c2 = (tid & 15) * 2;
    const int s0 = tid >> 4;
    #pragma unroll
    for (int it = 0; it < 2; it++) {
        const int s = s0 + it * 16;
        const __half2 h = __floats2half2_rn(tile[c2][s], tile[c2 + 1][s]);
        *(__half2*)(op + (long)s * 256 + c2) = h;
    }
}

// ---------------- main kernel: R2 mapping, fp16 HFMA2 tap combine ----------------
#define SB_PITCH 132
__global__ __launch_bounds__(256) void msroi5(
    const float* __restrict__ rois, float* __restrict__ out)
{
    __shared__ int   sxo0[14], sxo1[14], syo0[14], syo1[14];
    __shared__ float swx0[14], swx1[14], swy0[14], swy1[14];
    __shared__ float sbuf[49 * SB_PITCH];           // one 128-ch output tile

    const int roi = blockIdx.x;                     // b*256 + n
    const int b   = roi >> 8;
    const int tid = threadIdx.x;

    if (tid < 28) {
        const float rx1 = rois[roi*4+0], ry1 = rois[roi*4+1];
        const float rx2 = rois[roi*4+2], ry2 = rois[roi*4+3];
        const float area = (rx2 - rx1) * (ry2 - ry1);
        float lv = floorf(4.0f + log2f(sqrtf(area) / 224.0f + 1e-6f));
        lv = fminf(fmaxf(lv, 2.0f), 6.0f);
        const int lvl = (int)lv - 2;

        int H, base; float scale;
        switch (lvl) {
            case 0:  H = 128; base = FB0; scale = 0.25f;     break;
            case 1:  H = 64;  base = FB1; scale = 0.125f;    break;
            case 2:  H = 32;  base = FB2; scale = 0.0625f;   break;
            case 3:  H = 16;  base = FB3; scale = 0.03125f;  break;
            default: H = 8;   base = FB4; scale = 0.015625f; break;
        }
        const float x1 = rx1 * scale, y1 = ry1 * scale;
        const float bw = fmaxf(rx2 * scale - x1, 1.0f) / 7.0f;
        const float bh = fmaxf(ry2 * scale - y1, 1.0f) / 7.0f;

        const bool isY = tid >= 14;
        const int  i   = isY ? tid - 14 : tid;
        const float g = 0.25f + 0.5f * (float)i;              // == k + (sr+0.5)/2
        const float p = isY ? (y1 + g * bh) : (x1 + g * bw);
        const float v = (p >= -1.0f && p <= (float)H) ? 0.5f : 0.0f;  // validity * sqrt(2x2 mean)
        const float pc = fminf(fmaxf(p, 0.0f), (float)(H - 1));
        const float pf = floorf(pc);
        const float l  = pc - pf;
        const int p0 = (int)pf;
        const int p1 = min(p0 + 1, H - 1);
        if (isY) {
            syo0[i] = base + ((b * H + p0) * H) * 256;
            syo1[i] = base + ((b * H + p1) * H) * 256;
            swy0[i] = (1.0f - l) * v;  swy1[i] = l * v;
        } else {
            sxo0[i] = p0 * 256;  sxo1[i] = p1 * 256;
            swx0[i] = (1.0f - l) * v;  swx1[i] = l * v;
        }
    }
    __syncthreads();

    const int c8 = (tid & 15) * 8;   // 8-channel oct within a 128-ch tile
    const int bg = tid >> 4;         // 16 bin groups

    for (int ct = 0; ct < 2; ct++) {
        const int cofs = ct * 128 + c8;

        for (int bin = bg; bin < 49; bin += 16) {
            const int oy = bin / 7;
            const int ox = bin - oy * 7;
            unsigned long long acc0 = 0ull, acc1 = 0ull, acc2 = 0ull, acc3 = 0ull;
            #pragma unroll
            for (int sy = 0; sy < 2; sy++) {
                const int gy = 2 * oy + sy;
                const __half* __restrict__ r0 = g_fth + syo0[gy] + cofs;
                const __half* __restrict__ r1 = g_fth + syo1[gy] + cofs;
                const float wy0 = swy0[gy], wy1 = swy1[gy];
                #pragma unroll
                for (int sx = 0; sx < 2; sx++) {
                    const int gx  = 2 * ox + sx;
                    const int xo0 = sxo0[gx], xo1 = sxo1[gx];
                    const __half2 W00 = __float2half2_rn(wy0 * swx0[gx]);
                    const __half2 W01 = __float2half2_rn(wy0 * swx1[gx]);
                    const __half2 W10 = __float2half2_rn(wy1 * swx0[gx]);
                    const __half2 W11 = __float2half2_rn(wy1 * swx1[gx]);
                    const uint4 q00 = *(const uint4*)(r0 + xo0);
                    const uint4 q01 = *(const uint4*)(r0 + xo1);
                    const uint4 q10 = *(const uint4*)(r1 + xo0);
                    const uint4 q11 = *(const uint4*)(r1 + xo1);
                    #pragma unroll
                    for (int k = 0; k < 4; k++) {
                        const __half2 h00 = ((const __half2*)&q00)[k];
                        const __half2 h01 = ((const __half2*)&q01)[k];
                        const __half2 h10 = ((const __half2*)&q10)[k];
                        const __half2 h11 = ((const __half2*)&q11)[k];
                        const __half2 s = __hfma2(h00, W00,
                                          __hfma2(h01, W01,
                                          __hfma2(h10, W10,
                                          __hmul2(h11, W11))));
                        const unsigned long long sf = h2f2(s);
                        switch (k) {
                            case 0: addf2(acc0, sf); break;
                            case 1: addf2(acc1, sf); break;
                            case 2: addf2(acc2, sf); break;
                            default: addf2(acc3, sf); break;
                        }
                    }
                }
            }
            const float2 p0 = unpackf2(acc0);
            const float2 p1 = unpackf2(acc1);
            const float2 p2 = unpackf2(acc2);
            const float2 p3 = unpackf2(acc3);
            float* sp = sbuf + bin * SB_PITCH + c8;
            *(float4*)(sp    ) = make_float4(p0.x, p0.y, p1.x, p1.y);
            *(float4*)(sp + 4) = make_float4(p2.x, p2.y, p3.x, p3.y);
        }
        __syncthreads();

        // coalesced rewrite of this 128-channel tile into [c][bin] order
        float* __restrict__ op = out + (long)roi * 12544 + ct * 6272;
        for (int o = tid; o < 6272; o += 256) {
            const int c2 = o / 49;
            const int b2 = o - c2 * 49;
            op[o] = sbuf[b2 * SB_PITCH + c2];
        }
        __syncthreads();
    }
}

extern "C" void kernel_launch(void* const* d_in, const int* in_sizes, int n_in,
                              void* d_out, int out_size) {
    const float* f0   = (const float*)d_in[0];
    const float* f1   = (const float*)d_in[1];
    const float* f2   = (const float*)d_in[2];
    const float* f3   = (const float*)d_in[3];
    const float* f4   = (const float*)d_in[4];
    const float* rois = (const float*)d_in[5];
    float* out        = (float*)d_out;

    transpose_all<<<21824, 256>>>(f0, f1, f2, f3, f4);
    msroi5<<<1024, 256>>>(rois, out);
}

// round 8
// speedup vs baseline: 2.6032x; 1.1318x over previous
#include <cuda_runtime.h>
#include <cuda_fp16.h>
#include <cuda_bf16.h>

// Channels-last fp16 scratch: per level [B][H*W][256]. Bases in elements.
#define FB0 0
#define FB1 16777216            // + 4*128*128*256
#define FB2 20971520            // + 4*64*64*256
#define FB3 22020096            // + 4*32*32*256
#define FB4 22282240            // + 4*16*16*256
#define FT_TOTAL 22347776       // + 4*8*8*256

__device__ __half g_fth[FT_TOTAL];   // ~44.7 MB — resident in L2

// half2 -> packed f32x2 (2 CVT)
__device__ __forceinline__ float2 h2f2(__half2 h) {
    float2 f;
    unsigned int u = *(unsigned int*)&h;
    asm("{.reg .b16 a, b;\n\t"
        "mov.b32 {a, b}, %2;\n\t"
        "cvt.f32.f16 %0, a;\n\t"
        "cvt.f32.f16 %1, b;}\n\t" : "=f"(f.x), "=f"(f.y) : "r"(u));
    return f;
}

// ---------------- merged transpose: [b][c][s] -> [b][s][c] fp16, 32ch x 128s tiles ----------------
__global__ __launch_bounds__(256) void transpose_all(
    const float* __restrict__ f0, const float* __restrict__ f1,
    const float* __restrict__ f2, const float* __restrict__ f3,
    const float* __restrict__ f4)
{
    __shared__ float tile[32 * 129];    // pitch 129: conflict-free both phases
    int bid = blockIdx.x;
    const float* in; int HH, base, ntile;
    if (bid < 4096)      { in = f0; HH = 16384; base = FB0; ntile = 128; }
    else if (bid < 5120) { in = f1; HH = 4096;  base = FB1; ntile = 32; bid -= 4096; }
    else if (bid < 5376) { in = f2; HH = 1024;  base = FB2; ntile = 8;  bid -= 5120; }
    else if (bid < 5440) { in = f3; HH = 256;   base = FB3; ntile = 2;  bid -= 5376; }
    else                 { in = f4; HH = 64;    base = FB4; ntile = 1;  bid -= 5440; }

    const int st = bid % ntile;                 // spatial tile (128 wide)
    const int r  = bid / ntile;
    const int ct = r & 7;                       // channel tile (8 x 32ch)
    const int b  = r >> 3;                      // batch
    const int tid = threadIdx.x;
    const int s_base = st * 128;

    // Load phase: thread (lc = ch, q): 4 float4 loads.
    const int lc = tid >> 3;
    const int q  = tid & 7;
    const float* ip = in + (long)(b * 256 + ct * 32 + lc) * HH + s_base;
    #pragma unroll
    for (int j = 0; j < 4; j++) {
        const int s = q * 4 + j * 32;
        if (s_base + s < HH) {
            const float4 v = *(const float4*)(ip + s);
            float* tp = tile + lc * 129 + s;
            tp[0] = v.x; tp[1] = v.y; tp[2] = v.z; tp[3] = v.w;
        }
    }
    __syncthreads();

    // Store phase: thread (s, 16-ch half): pack 16 ch -> 2 uint4 stores.
    const int s_l  = tid >> 1;
    const int half = tid & 1;
    if (s_base + s_l < HH) {
        const int c16 = half * 16;
        __half2 hs[8];
        #pragma unroll
        for (int i = 0; i < 8; i++)
            hs[i] = __floats2half2_rn(tile[(c16 + 2*i) * 129 + s_l],
                                      tile[(c16 + 2*i + 1) * 129 + s_l]);
        __half* dst = g_fth + base + ((long)b * HH + s_base + s_l) * 256 + ct * 32 + c16;
        *(uint4*)(dst)     = ((const uint4*)hs)[0];
        *(uint4*)(dst + 8) = ((const uint4*)hs)[1];
    }
}

// ---------------- main kernel: block = (ROI, 128-ch tile), fp16 chained accumulation ----------------
#define SB_PITCH 132
__global__ __launch_bounds__(256) void msroi6(
    const float* __restrict__ rois, float* __restrict__ out)
{
    __shared__ int   sxo0[14], sxo1[14], syo0[14], syo1[14];
    __shared__ float swx0[14], swx1[14], swy0[14], swy1[14];
    __shared__ float sbuf[49 * SB_PITCH];           // one 128-ch output tile

    const int roi = blockIdx.x >> 1;                // b*256 + n
    const int ct  = blockIdx.x & 1;                 // channel tile
    const int b   = roi >> 8;
    const int tid = threadIdx.x;

    if (tid < 28) {
        const float rx1 = rois[roi*4+0], ry1 = rois[roi*4+1];
        const float rx2 = rois[roi*4+2], ry2 = rois[roi*4+3];
        const float area = (rx2 - rx1) * (ry2 - ry1);
        float lv = floorf(4.0f + log2f(sqrtf(area) / 224.0f + 1e-6f));
        lv = fminf(fmaxf(lv, 2.0f), 6.0f);
        const int lvl = (int)lv - 2;

        int H, base; float scale;
        switch (lvl) {
            case 0:  H = 128; base = FB0; scale = 0.25f;     break;
            case 1:  H = 64;  base = FB1; scale = 0.125f;    break;
            case 2:  H = 32;  base = FB2; scale = 0.0625f;   break;
            case 3:  H = 16;  base = FB3; scale = 0.03125f;  break;
            default: H = 8;   base = FB4; scale = 0.015625f; break;
        }
        const float x1 = rx1 * scale, y1 = ry1 * scale;
        const float bw = fmaxf(rx2 * scale - x1, 1.0f) / 7.0f;
        const float bh = fmaxf(ry2 * scale - y1, 1.0f) / 7.0f;

        const bool isY = tid >= 14;
        const int  i   = isY ? tid - 14 : tid;
        const float g = 0.25f + 0.5f * (float)i;              // == k + (sr+0.5)/2
        const float p = isY ? (y1 + g * bh) : (x1 + g * bw);
        const float v = (p >= -1.0f && p <= (float)H) ? 0.5f : 0.0f;  // validity * sqrt(2x2 mean)
        const float pc = fminf(fmaxf(p, 0.0f), (float)(H - 1));
        const float pf = floorf(pc);
        const float l  = pc - pf;
        const int p0 = (int)pf;
        const int p1 = min(p0 + 1, H - 1);
        if (isY) {
            syo0[i] = base + ((b * H + p0) * H) * 256;
            syo1[i] = base + ((b * H + p1) * H) * 256;
            swy0[i] = (1.0f - l) * v;  swy1[i] = l * v;
        } else {
            sxo0[i] = p0 * 256;  sxo1[i] = p1 * 256;
            swx0[i] = (1.0f - l) * v;  swx1[i] = l * v;
        }
    }
    __syncthreads();

    const int c8   = (tid & 15) * 8;   // 8-channel oct within the 128-ch tile
    const int bg   = tid >> 4;         // 16 bin groups
    const int cofs = ct * 128 + c8;

    for (int bin = bg; bin < 49; bin += 16) {
        const int oy = bin / 7;
        const int ox = bin - oy * 7;
        const __half2 hz = __float2half2_rn(0.0f);
        __half2 acc0 = hz, acc1 = hz, acc2 = hz, acc3 = hz;
        #pragma unroll
        for (int sy = 0; sy < 2; sy++) {
            const int gy = 2 * oy + sy;
            const __half* __restrict__ r0 = g_fth + syo0[gy] + cofs;
            const __half* __restrict__ r1 = g_fth + syo1[gy] + cofs;
            const float wy0 = swy0[gy], wy1 = swy1[gy];
            #pragma unroll
            for (int sx = 0; sx < 2; sx++) {
                const int gx  = 2 * ox + sx;
                const int xo0 = sxo0[gx], xo1 = sxo1[gx];
                const __half2 W00 = __float2half2_rn(wy0 * swx0[gx]);
                const __half2 W01 = __float2half2_rn(wy0 * swx1[gx]);
                const __half2 W10 = __float2half2_rn(wy1 * swx0[gx]);
                const __half2 W11 = __float2half2_rn(wy1 * swx1[gx]);
                const uint4 q00 = *(const uint4*)(r0 + xo0);
                const uint4 q01 = *(const uint4*)(r0 + xo1);
                const uint4 q10 = *(const uint4*)(r1 + xo0);
                const uint4 q11 = *(const uint4*)(r1 + xo1);
                #pragma unroll
                for (int k = 0; k < 4; k++) {
                    const __half2 h00 = ((const __half2*)&q00)[k];
                    const __half2 h01 = ((const __half2*)&q01)[k];
                    const __half2 h10 = ((const __half2*)&q10)[k];
                    const __half2 h11 = ((const __half2*)&q11)[k];
                    __half2 a = (k == 0) ? acc0 : (k == 1) ? acc1 : (k == 2) ? acc2 : acc3;
                    a = __hfma2(h00, W00,
                        __hfma2(h01, W01,
                        __hfma2(h10, W10,
                        __hfma2(h11, W11, a))));
                    if (k == 0) acc0 = a; else if (k == 1) acc1 = a;
                    else if (k == 2) acc2 = a; else acc3 = a;
                }
            }
        }
        const float2 p0 = h2f2(acc0);
        const float2 p1 = h2f2(acc1);
        const float2 p2 = h2f2(acc2);
        const float2 p3 = h2f2(acc3);
        float* sp = sbuf + bin * SB_PITCH + c8;
        *(float4*)(sp    ) = make_float4(p0.x, p0.y, p1.x, p1.y);
        *(float4*)(sp + 4) = make_float4(p2.x, p2.y, p3.x, p3.y);
    }
    __syncthreads();

    // coalesced rewrite of this 128-channel tile into [c][bin] order
    float* __restrict__ op = out + (long)roi * 12544 + ct * 6272;
    for (int o = tid; o < 6272; o += 256) {
        const int c2 = o / 49;
        const int b2 = o - c2 * 49;
        op[o] = sbuf[b2 * SB_PITCH + c2];
    }
}

extern "C" void kernel_launch(void* const* d_in, const int* in_sizes, int n_in,
                              void* d_out, int out_size) {
    const float* f0   = (const float*)d_in[0];
    const float* f1   = (const float*)d_in[1];
    const float* f2   = (const float*)d_in[2];
    const float* f3   = (const float*)d_in[3];
    const float* f4   = (const float*)d_in[4];
    const float* rois = (const float*)d_in[5];
    float* out        = (float*)d_out;

    transpose_all<<<5472, 256>>>(f0, f1, f2, f3, f4);
    msroi6<<<2048, 256>>>(rois, out);
}